// round 16
// baseline (speedup 1.0000x reference)
#include <cuda_runtime.h>
#include <cuda_fp16.h>

#define N_NODES 20000
#define N_EDGES 200000
#define N_TRIP  400000
#define HID 128
#define DOWN 32
#define CO 64
#define DR 16
#define SLOT_CAP 32

// mega-kernel role ranges: [fill | node | co | aggzero]
#define FILL_BLKS 1563
#define NODE_BLKS 625
#define CO_BLKS   5000
#define AGG_BLKS  157
#define MEGA_BLKS (FILL_BLKS + NODE_BLKS + CO_BLKS + AGG_BLKS)

// mega dynamic smem in BYTES: co role is largest:
// sW1h 16384 | sW2h 8192 | sX 16384 | sH 34816  = 75776 B -> 3 blocks/SM
#define MEGA_SMEM_BYTES 75776

// ---------------- device scratch (no allocations allowed) ----------------
__device__ float  g_xd[N_NODES * DOWN];          // 2.56 MB
// lane-contiguous fp16 layout: uint2 #(node*128 + l*4 + i) holds
// (as 4 halfs) floats [(l&1)*16 + i*4 .. +4) of row r = l>>1 of c[node].
// A lane's 16 floats are 32 contiguous bytes -> 2x LDG.128 per row-half.
__device__ __half g_c[N_NODES * DR * DOWN];      // 20.48 MB
__device__ float  g_agg[N_NODES * DOWN];         // 2.56 MB
__device__ int    g_cnt[N_EDGES];                // per-edge triplet count
__device__ int    g_slot[N_EDGES * SLOT_CAP];    // slotted CSR (25.6 MB)

__device__ __forceinline__ float silu_f(float v) {
    return v / (1.0f + __expf(-v));
}

__device__ __forceinline__ uint2 pack_h4(float x, float y, float z, float w) {
    __half2 a = __floats2half2_rn(x, y);
    __half2 b = __floats2half2_rn(z, w);
    return make_uint2(*reinterpret_cast<unsigned*>(&a),
                      *reinterpret_cast<unsigned*>(&b));
}

// ---------------- K0: init cnt=0 (g_agg zeroed inside mega) ----------------
__global__ void init_kernel() {
    int i = blockIdx.x * blockDim.x + threadIdx.x;
    if (i < N_EDGES) g_cnt[i] = 0;
}

// ---------------- mega role: fill slotted CSR ------------------------------
__device__ __forceinline__ void fill_part(int lb, const int* __restrict__ e_ji) {
    int i = lb * 256 + threadIdx.x;
    if (i >= N_TRIP) return;
    int ji = e_ji[i];
    int p = atomicAdd(&g_cnt[ji], 1);
    if (p < SLOT_CAP) g_slot[ji * SLOT_CAP + p] = i;
}

// ---------------- mega role: zero g_agg (needed only before fused_edge) ----
__device__ __forceinline__ void agg_part(int lb) {
    int base = lb * 4096 + threadIdx.x * 4;
    float4 z = make_float4(0.f, 0.f, 0.f, 0.f);
    #pragma unroll
    for (int m = 0; m < 4; m++) {
        int idx = base + m * 1024;
        if (idx < N_NODES * DOWN)
            *reinterpret_cast<float4*>(&g_agg[idx]) = z;
    }
}

// ---------------- mega role: node MLP (256 thr, 32 nodes/block) ------------
// weights fp16 in smem; activations + accumulate fp32
__device__ __forceinline__ void node_part(int lb,
                                          const float* __restrict__ x,
                                          const float* __restrict__ W1,
                                          const float* __restrict__ b1,
                                          const float* __restrict__ W2,
                                          const float* __restrict__ b2,
                                          char* smem) {
    __half* sW1h = reinterpret_cast<__half*>(smem);           // 32768 B
    __half* sW2h = reinterpret_cast<__half*>(smem + 32768);   //  8192 B
    float*  sb1  = reinterpret_cast<float*>(smem + 40960);    //   512 B
    float*  sb2  = reinterpret_cast<float*>(smem + 41472);    //   128 B
    int tid  = threadIdx.x;
    int half = tid >> 7;
    int t    = tid & 127;
    float* h0 = reinterpret_cast<float*>(smem + 41600) + half * 1024;  // 512 each
    float* h1 = h0 + 512;

    {
        const float4* W14 = reinterpret_cast<const float4*>(W1);
        uint2* v = reinterpret_cast<uint2*>(sW1h);
        for (int i = tid; i < 4096; i += 256) {
            float4 w = W14[i];
            v[i] = pack_h4(w.x, w.y, w.z, w.w);
        }
        const float4* W24 = reinterpret_cast<const float4*>(W2);
        uint2* v2 = reinterpret_cast<uint2*>(sW2h);
        for (int i = tid; i < 1024; i += 256) {
            float4 w = W24[i];
            v2[i] = pack_h4(w.x, w.y, w.z, w.w);
        }
    }
    if (tid < 128) sb1[tid] = b1[tid];
    else if (tid < 160) sb2[tid - 128] = b2[tid - 128];
    __syncthreads();

    int base = lb * 32 + half * 16;
    for (int n0 = 0; n0 < 16; n0 += 4) {
        float4 hv;
        hv.x = silu_f(x[(base + n0 + 0) * HID + t]);
        hv.y = silu_f(x[(base + n0 + 1) * HID + t]);
        hv.z = silu_f(x[(base + n0 + 2) * HID + t]);
        hv.w = silu_f(x[(base + n0 + 3) * HID + t]);
        *reinterpret_cast<float4*>(&h0[t * 4]) = hv;
        __syncthreads();

        float4 acc = make_float4(sb1[t], sb1[t], sb1[t], sb1[t]);
        #pragma unroll 8
        for (int k = 0; k < 128; k++) {
            float w = __half2float(sW1h[k * 128 + t]);
            float4 h = *reinterpret_cast<const float4*>(&h0[k * 4]);
            acc.x = fmaf(h.x, w, acc.x);
            acc.y = fmaf(h.y, w, acc.y);
            acc.z = fmaf(h.z, w, acc.z);
            acc.w = fmaf(h.w, w, acc.w);
        }
        float4 s1 = make_float4(silu_f(acc.x), silu_f(acc.y), silu_f(acc.z), silu_f(acc.w));
        *reinterpret_cast<float4*>(&h1[t * 4]) = s1;
        __syncthreads();

        if (t < 32) {
            float4 a2 = make_float4(sb2[t], sb2[t], sb2[t], sb2[t]);
            #pragma unroll 8
            for (int k = 0; k < 128; k++) {
                float w = __half2float(sW2h[k * 32 + t]);
                float4 h = *reinterpret_cast<const float4*>(&h1[k * 4]);
                a2.x = fmaf(h.x, w, a2.x);
                a2.y = fmaf(h.y, w, a2.y);
                a2.z = fmaf(h.z, w, a2.z);
                a2.w = fmaf(h.w, w, a2.w);
            }
            g_xd[(base + n0 + 0) * DOWN + t] = a2.x;
            g_xd[(base + n0 + 1) * DOWN + t] = a2.y;
            g_xd[(base + n0 + 2) * DOWN + t] = a2.z;
            g_xd[(base + n0 + 3) * DOWN + t] = a2.w;
        }
        __syncthreads();
    }
}

// ---------------- mega role: coeffs MLP (256 thr, 64 rows) -----------------
// weights fp16 in smem; activations + accumulate fp32; 3 blocks/SM
__device__ __forceinline__ void co_part(int lb,
                                        const float* __restrict__ cin,
                                        const float* __restrict__ W1,
                                        const float* __restrict__ W2,
                                        char* smem) {
    __half* sW1h = reinterpret_cast<__half*>(smem);           // [k=64][col=128] 16384 B
    __half* sW2h = reinterpret_cast<__half*>(smem + 16384);   // [k=128][col=32]  8192 B
    float*  sX   = reinterpret_cast<float*>(smem + 24576);    // [k=64][row=64]  16384 B
    float*  sH   = reinterpret_cast<float*>(smem + 40960);    // [hid=128][pad68] 34816 B

    int tid = threadIdx.x;
    int rowbase = lb * 64;

    {
        const float4* W14 = reinterpret_cast<const float4*>(W1);
        uint2* v = reinterpret_cast<uint2*>(sW1h);
        #pragma unroll
        for (int i = tid; i < 2048; i += 256) {
            float4 w = W14[i];
            v[i] = pack_h4(w.x, w.y, w.z, w.w);
        }
        const float4* W24 = reinterpret_cast<const float4*>(W2);
        uint2* v2 = reinterpret_cast<uint2*>(sW2h);
        #pragma unroll
        for (int i = tid; i < 1024; i += 256) {
            float4 w = W24[i];
            v2[i] = pack_h4(w.x, w.y, w.z, w.w);
        }
    }

    {
        int r  = tid & 63;
        int kc = tid >> 6;
        const float4* cin4 = reinterpret_cast<const float4*>(cin + (size_t)(rowbase + r) * CO);
        #pragma unroll
        for (int m = 0; m < 4; m++) {
            float4 v = cin4[kc * 4 + m];
            int k0 = kc * 16 + m * 4;
            sX[(k0 + 0) * 64 + r] = silu_f(v.x);
            sX[(k0 + 1) * 64 + r] = silu_f(v.y);
            sX[(k0 + 2) * 64 + r] = silu_f(v.z);
            sX[(k0 + 3) * 64 + r] = silu_f(v.w);
        }
    }
    __syncthreads();

    int tr = tid & 15;
    int tc = tid >> 4;

    float acc[4][8];
    #pragma unroll
    for (int i = 0; i < 4; i++)
        #pragma unroll
        for (int j = 0; j < 8; j++) acc[i][j] = 0.f;

    const float4* sX4  = reinterpret_cast<const float4*>(sX);
    const uint4*  sW1q = reinterpret_cast<const uint4*>(sW1h);   // 16 uint4 per k-row
    #pragma unroll 4
    for (int k = 0; k < 64; k++) {
        float4 a  = sX4[k * 16 + tr];
        uint4  bq = sW1q[k * 16 + tc];           // 8 halfs: cols tc*8..+7
        float2 f0 = __half22float2(*reinterpret_cast<__half2*>(&bq.x));
        float2 f1 = __half22float2(*reinterpret_cast<__half2*>(&bq.y));
        float2 f2 = __half22float2(*reinterpret_cast<__half2*>(&bq.z));
        float2 f3 = __half22float2(*reinterpret_cast<__half2*>(&bq.w));
        float av[4] = {a.x, a.y, a.z, a.w};
        float bv[8] = {f0.x, f0.y, f1.x, f1.y, f2.x, f2.y, f3.x, f3.y};
        #pragma unroll
        for (int i = 0; i < 4; i++)
            #pragma unroll
            for (int j = 0; j < 8; j++)
                acc[i][j] = fmaf(av[i], bv[j], acc[i][j]);
    }

    float4* sH4 = reinterpret_cast<float4*>(sH);
    #pragma unroll
    for (int j = 0; j < 8; j++) {
        int col = tc * 8 + j;
        float4 v = make_float4(silu_f(acc[0][j]), silu_f(acc[1][j]),
                               silu_f(acc[2][j]), silu_f(acc[3][j]));
        sH4[col * 17 + tr] = v;
    }
    __syncthreads();

    float a20 = 0.f, a21 = 0.f, a22 = 0.f, a23 = 0.f;
    float a30 = 0.f, a31 = 0.f, a32 = 0.f, a33 = 0.f;
    const unsigned* sW2u = reinterpret_cast<const unsigned*>(sW2h);  // 16 per k-row
    #pragma unroll 8
    for (int k = 0; k < 128; k++) {
        float4 a = sH4[k * 17 + tr];
        unsigned bu = sW2u[k * 16 + tc];
        float2 b = __half22float2(*reinterpret_cast<__half2*>(&bu));
        a20 = fmaf(a.x, b.x, a20);
        a21 = fmaf(a.y, b.x, a21);
        a22 = fmaf(a.z, b.x, a22);
        a23 = fmaf(a.w, b.x, a23);
        a30 = fmaf(a.x, b.y, a30);
        a31 = fmaf(a.y, b.y, a31);
        a32 = fmaf(a.z, b.y, a32);
        a33 = fmaf(a.w, b.y, a33);
    }

    float* sOut = sX;   // sX dead after layer-1 sync
    int r0 = tr * 4;
    int c0 = tc * 2;
    sOut[(r0 + 0) * 32 + c0]     = a20;
    sOut[(r0 + 1) * 32 + c0]     = a21;
    sOut[(r0 + 2) * 32 + c0]     = a22;
    sOut[(r0 + 3) * 32 + c0]     = a23;
    sOut[(r0 + 0) * 32 + c0 + 1] = a30;
    sOut[(r0 + 1) * 32 + c0 + 1] = a31;
    sOut[(r0 + 2) * 32 + c0 + 1] = a32;
    sOut[(r0 + 3) * 32 + c0 + 1] = a33;
    __syncthreads();

    // epilogue: lane-contiguous layout: uint2 index w = l*4 + i
    const float4* sOut4 = reinterpret_cast<const float4*>(sOut);
    uint2* outh = reinterpret_cast<uint2*>(g_c);
    int nodebase = lb * 4;
    #pragma unroll
    for (int mm = 0; mm < 2; mm++) {
        int m  = tid + mm * 256;
        int q  = m >> 7;
        int w  = m & 127;
        int l  = w >> 2;          // chunk lane
        int i  = w & 3;           // quarter
        int rr = l >> 1;
        int hf = l & 1;
        float4 vv = sOut4[(q * 16 + rr) * 8 + hf * 4 + i];
        outh[(size_t)(nodebase + q) * 128 + w] = pack_h4(vv.x, vv.y, vv.z, vv.w);
    }
}

// ---------------- mega kernel: fill | node | co | aggzero ------------------
__global__ __launch_bounds__(256) void mega_kernel(
    const float* __restrict__ x,
    const float* __restrict__ coeffs,
    const int* __restrict__ e_ji,
    const float* __restrict__ Wn1,
    const float* __restrict__ bn1,
    const float* __restrict__ Wn2,
    const float* __restrict__ bn2,
    const float* __restrict__ Wc1,
    const float* __restrict__ Wc2) {
    extern __shared__ char smem[];
    int bid = blockIdx.x;
    if (bid < FILL_BLKS) {
        fill_part(bid, e_ji);
    } else if (bid < FILL_BLKS + NODE_BLKS) {
        node_part(bid - FILL_BLKS, x, Wn1, bn1, Wn2, bn2, smem);
    } else if (bid < FILL_BLKS + NODE_BLKS + CO_BLKS) {
        co_part(bid - FILL_BLKS - NODE_BLKS, coeffs, Wc1, Wc2, smem);
    } else {
        agg_part(bid - FILL_BLKS - NODE_BLKS - CO_BLKS);
    }
}

// unpack one uint4 (8 halfs = 2 quarters) to 8 floats
__device__ __forceinline__ void unpack8(uint4 u, float* o) {
    float2 f0 = __half22float2(*reinterpret_cast<__half2*>(&u.x));
    float2 f1 = __half22float2(*reinterpret_cast<__half2*>(&u.y));
    float2 f2 = __half22float2(*reinterpret_cast<__half2*>(&u.z));
    float2 f3 = __half22float2(*reinterpret_cast<__half2*>(&u.w));
    o[0] = f0.x; o[1] = f0.y; o[2] = f1.x; o[3] = f1.y;
    o[4] = f2.x; o[5] = f2.y; o[6] = f3.x; o[7] = f3.y;
}

// ---------------- K3: fused triplet + edge + aggregation ------------------
// warp per edge; lane pair (2r, 2r+1) owns DR row r (16 h-values each).
// c rows read as 2x LDG.128 per node per lane (lane-contiguous layout).
__global__ __launch_bounds__(256) void fused_edge_kernel(
    const float* __restrict__ robs,
    const float* __restrict__ shbs,
    const int* __restrict__ idx_j,
    const int* __restrict__ idx_k,
    const int* __restrict__ e_kj,
    const int* __restrict__ edge_index) {
    int e    = (blockIdx.x * blockDim.x + threadIdx.x) >> 5;
    int lane = threadIdx.x & 31;
    if (e >= N_EDGES) return;

    const uint4* cq = reinterpret_cast<const uint4*>(g_c);   // 64 uint4 per node
    int hr = lane >> 1;

    int n   = g_cnt[e];
    int src = edge_index[e];
    int dst = edge_index[N_EDGES + e];
    float wr = robs[e * DR + hr];
    const int* sl = g_slot + e * SLOT_CAP;

    float tw[16];
    #pragma unroll
    for (int i = 0; i < 16; i++) tw[i] = 0.f;

    #pragma unroll 2
    for (int ii = 0; ii < n; ii++) {
        int t  = sl[ii];
        int j  = idx_j[t];
        int k  = idx_k[t];
        int kj = e_kj[t];
        float w = shbs[t * DR + hr] * robs[kj * DR + hr];

        uint4 ka = cq[(size_t)k * 64 + lane * 2];
        uint4 kb = cq[(size_t)k * 64 + lane * 2 + 1];
        uint4 ja = cq[(size_t)j * 64 + lane * 2];
        uint4 jb = cq[(size_t)j * 64 + lane * 2 + 1];

        float a[16], b[16];
        unpack8(ka, a);     unpack8(kb, a + 8);
        unpack8(ja, b);     unpack8(jb, b + 8);

        float v[16];
        #pragma unroll
        for (int i = 0; i < 16; i++) v[i] = fmaf(a[i], b[i], a[i]);

        float p0 = 0.f, p1 = 0.f, p2 = 0.f, p3 = 0.f;
        #pragma unroll
        for (int i = 0; i < 4; i++) {
            p0 = fmaf(v[i*4+0], v[i*4+0], p0);
            p1 = fmaf(v[i*4+1], v[i*4+1], p1);
            p2 = fmaf(v[i*4+2], v[i*4+2], p2);
            p3 = fmaf(v[i*4+3], v[i*4+3], p3);
        }
        float ss = (p0 + p1) + (p2 + p3);
        ss += __shfl_xor_sync(0xffffffffu, ss, 1);
        float scale = w / fmaxf(sqrtf(ss), 1e-12f);
        #pragma unroll
        for (int i = 0; i < 16; i++) tw[i] = fmaf(scale, v[i], tw[i]);
    }

    // -------- edge interaction --------
    uint4 da = cq[(size_t)dst * 64 + lane * 2];
    uint4 db = cq[(size_t)dst * 64 + lane * 2 + 1];
    uint4 sa = cq[(size_t)src * 64 + lane * 2];
    uint4 sb = cq[(size_t)src * 64 + lane * 2 + 1];

    float a[16], b[16];
    unpack8(da, a);     unpack8(db, a + 8);
    unpack8(sa, b);     unpack8(sb, b + 8);

    float val[16];
    #pragma unroll
    for (int i = 0; i < 16; i++) val[i] = fmaf(a[i], b[i], a[i]) * tw[i];

    float p0 = 0.f, p1 = 0.f, p2 = 0.f, p3 = 0.f;
    #pragma unroll
    for (int i = 0; i < 4; i++) {
        p0 = fmaf(val[i*4+0], val[i*4+0], p0);
        p1 = fmaf(val[i*4+1], val[i*4+1], p1);
        p2 = fmaf(val[i*4+2], val[i*4+2], p2);
        p3 = fmaf(val[i*4+3], val[i*4+3], p3);
    }
    float ss = (p0 + p1) + (p2 + p3);
    ss += __shfl_xor_sync(0xffffffffu, ss, 1);
    float factor = wr / fmaxf(sqrtf(ss), 1e-12f);
    #pragma unroll
    for (int i = 0; i < 16; i++) val[i] *= factor;

    #pragma unroll
    for (int st = 0; st < 4; st++) {
        const int s  = 2 << st;
        const int n2 = 8 >> st;
        bool up = (lane & s) != 0;
        #pragma unroll
        for (int m = 0; m < n2; m++) {
            float send = up ? val[m] : val[m + n2];
            float recv = __shfl_xor_sync(0xffffffffu, send, s);
            val[m] = (up ? val[m + n2] : val[m]) + recv;
        }
    }
    float acc = val[0];
    int idx = ((lane >> 1) & 1) * 8 + ((lane >> 2) & 1) * 4 +
              ((lane >> 3) & 1) * 2 + ((lane >> 4) & 1);
    int h = (lane & 1) * 16 + idx;

    float sq = acc * acc;
    #pragma unroll
    for (int m = 1; m < 32; m <<= 1) sq += __shfl_xor_sync(0xffffffffu, sq, m);
    float rd = acc / fmaxf(sqrtf(sq), 1e-12f);

    atomicAdd(&g_agg[src * DOWN + h], g_xd[dst * DOWN + h] * rd);
}

// ---------------- K5: up-projection (4-way ILP) ----------------------------
__global__ void up_kernel(const float* __restrict__ Wup,
                          float* __restrict__ out) {
    __shared__ float sW[DOWN * HID];
    __shared__ float sA[16 * DOWN];
    int t = threadIdx.x;
    for (int i = t; i < DOWN * HID; i += 128) sW[i] = Wup[i];
    int base = blockIdx.x * 16;
    for (int i = t; i < 512; i += 128) sA[i] = g_agg[base * DOWN + i];
    __syncthreads();

    for (int n = 0; n < 16; n += 4) {
        float a0 = 0.f, a1 = 0.f, a2 = 0.f, a3 = 0.f;
        #pragma unroll 8
        for (int d = 0; d < DOWN; d++) {
            float w = sW[d * HID + t];
            a0 = fmaf(sA[(n + 0) * DOWN + d], w, a0);
            a1 = fmaf(sA[(n + 1) * DOWN + d], w, a1);
            a2 = fmaf(sA[(n + 2) * DOWN + d], w, a2);
            a3 = fmaf(sA[(n + 3) * DOWN + d], w, a3);
        }
        out[(base + n + 0) * HID + t] = a0;
        out[(base + n + 1) * HID + t] = a1;
        out[(base + n + 2) * HID + t] = a2;
        out[(base + n + 3) * HID + t] = a3;
    }
}

// ---------------- launch ---------------------------------------------------
extern "C" void kernel_launch(void* const* d_in, const int* in_sizes, int n_in,
                              void* d_out, int out_size) {
    const float* x      = (const float*)d_in[0];
    const float* robs   = (const float*)d_in[1];
    const float* shbs   = (const float*)d_in[2];
    const float* coeffs = (const float*)d_in[3];
    const int*   eidx   = (const int*)d_in[4];
    const int*   idx_j  = (const int*)d_in[5];
    const int*   idx_k  = (const int*)d_in[6];
    const int*   e_kj   = (const int*)d_in[7];
    const int*   e_ji   = (const int*)d_in[8];
    const float* Wn1    = (const float*)d_in[9];
    const float* bn1    = (const float*)d_in[10];
    const float* Wn2    = (const float*)d_in[11];
    const float* bn2    = (const float*)d_in[12];
    const float* Wc1    = (const float*)d_in[13];
    const float* Wc2    = (const float*)d_in[14];
    const float* Wup    = (const float*)d_in[15];
    float* out = (float*)d_out;

    cudaFuncSetAttribute(mega_kernel, cudaFuncAttributeMaxDynamicSharedMemorySize, MEGA_SMEM_BYTES);

    // zero g_cnt only (must precede fill atomics); g_agg zeroed inside mega
    init_kernel<<<(N_EDGES + 255) / 256, 256>>>();

    // fill + node MLP + coeffs MLP + agg-zero in one grid (independent outputs)
    mega_kernel<<<MEGA_BLKS, 256, MEGA_SMEM_BYTES>>>(x, coeffs, e_ji,
                                                     Wn1, bn1, Wn2, bn2, Wc1, Wc2);

    // fused triplet + edge + aggregation: warp per edge
    fused_edge_kernel<<<N_EDGES / 8, 256>>>(robs, shbs, idx_j, idx_k, e_kj, eidx);

    // up-projection
    up_kernel<<<1250, 128>>>(Wup, out);
}

// round 17
// speedup vs baseline: 1.0365x; 1.0365x over previous
#include <cuda_runtime.h>
#include <cuda_fp16.h>

#define N_NODES 20000
#define N_EDGES 200000
#define N_TRIP  400000
#define HID 128
#define DOWN 32
#define CO 64
#define DR 16
#define SLOT_CAP 32

// mega-kernel role ranges: [fill | node | co | aggzero]
#define FILL_BLKS 1563
#define NODE_BLKS 625
#define CO_BLKS   5000
#define AGG_BLKS  157
#define MEGA_BLKS (FILL_BLKS + NODE_BLKS + CO_BLKS + AGG_BLKS)

// mega dynamic smem in BYTES: co role is largest:
// sW1h 16384 | sW2h 8192 | sX 16384 | sH 34816  = 75776 B -> 3 blocks/SM
#define MEGA_SMEM_BYTES 75776

// ---------------- device scratch (no allocations allowed) ----------------
__device__ float  g_xd[N_NODES * DOWN];          // 2.56 MB
// lane-contiguous fp16 layout: uint2 #(node*128 + l*4 + i) holds
// (as 4 halfs) floats [(l&1)*16 + i*4 .. +4) of row r = l>>1 of c[node].
__device__ __half g_c[N_NODES * DR * DOWN];      // 20.48 MB
__device__ float  g_agg[N_NODES * DOWN];         // 2.56 MB
__device__ int    g_cnt[N_EDGES];                // per-edge triplet count
// packed slot: {idx_j[t], idx_k[t], e_kj[t], t} — one load gives the whole
// triplet record, collapsing fe's L2 chain from 3 stages to 2.
__device__ int4   g_slot[N_EDGES * SLOT_CAP];    // 102.4 MB

__device__ __forceinline__ float silu_f(float v) {
    return v / (1.0f + __expf(-v));
}

__device__ __forceinline__ uint2 pack_h4(float x, float y, float z, float w) {
    __half2 a = __floats2half2_rn(x, y);
    __half2 b = __floats2half2_rn(z, w);
    return make_uint2(*reinterpret_cast<unsigned*>(&a),
                      *reinterpret_cast<unsigned*>(&b));
}

// ---------------- K0: init cnt=0 (g_agg zeroed inside mega) ----------------
__global__ void init_kernel() {
    int i = blockIdx.x * blockDim.x + threadIdx.x;
    if (i < N_EDGES) g_cnt[i] = 0;
}

// ---------------- mega role: fill slotted CSR (packed records) -------------
__device__ __forceinline__ void fill_part(int lb,
                                          const int* __restrict__ e_ji,
                                          const int* __restrict__ idx_j,
                                          const int* __restrict__ idx_k,
                                          const int* __restrict__ e_kj) {
    int i = lb * 256 + threadIdx.x;
    if (i >= N_TRIP) return;
    int ji = e_ji[i];
    int j  = idx_j[i];   // coalesced (i sequential)
    int k  = idx_k[i];
    int kj = e_kj[i];
    int p = atomicAdd(&g_cnt[ji], 1);
    if (p < SLOT_CAP) g_slot[ji * SLOT_CAP + p] = make_int4(j, k, kj, i);
}

// ---------------- mega role: zero g_agg (needed only before fused_edge) ----
__device__ __forceinline__ void agg_part(int lb) {
    int base = lb * 4096 + threadIdx.x * 4;
    float4 z = make_float4(0.f, 0.f, 0.f, 0.f);
    #pragma unroll
    for (int m = 0; m < 4; m++) {
        int idx = base + m * 1024;
        if (idx < N_NODES * DOWN)
            *reinterpret_cast<float4*>(&g_agg[idx]) = z;
    }
}

// ---------------- mega role: node MLP (256 thr, 32 nodes/block) ------------
// weights fp16 in smem; activations + accumulate fp32
__device__ __forceinline__ void node_part(int lb,
                                          const float* __restrict__ x,
                                          const float* __restrict__ W1,
                                          const float* __restrict__ b1,
                                          const float* __restrict__ W2,
                                          const float* __restrict__ b2,
                                          char* smem) {
    __half* sW1h = reinterpret_cast<__half*>(smem);           // 32768 B
    __half* sW2h = reinterpret_cast<__half*>(smem + 32768);   //  8192 B
    float*  sb1  = reinterpret_cast<float*>(smem + 40960);    //   512 B
    float*  sb2  = reinterpret_cast<float*>(smem + 41472);    //   128 B
    int tid  = threadIdx.x;
    int half = tid >> 7;
    int t    = tid & 127;
    float* h0 = reinterpret_cast<float*>(smem + 41600) + half * 1024;  // 512 each
    float* h1 = h0 + 512;

    {
        const float4* W14 = reinterpret_cast<const float4*>(W1);
        uint2* v = reinterpret_cast<uint2*>(sW1h);
        for (int i = tid; i < 4096; i += 256) {
            float4 w = W14[i];
            v[i] = pack_h4(w.x, w.y, w.z, w.w);
        }
        const float4* W24 = reinterpret_cast<const float4*>(W2);
        uint2* v2 = reinterpret_cast<uint2*>(sW2h);
        for (int i = tid; i < 1024; i += 256) {
            float4 w = W24[i];
            v2[i] = pack_h4(w.x, w.y, w.z, w.w);
        }
    }
    if (tid < 128) sb1[tid] = b1[tid];
    else if (tid < 160) sb2[tid - 128] = b2[tid - 128];
    __syncthreads();

    int base = lb * 32 + half * 16;
    for (int n0 = 0; n0 < 16; n0 += 4) {
        float4 hv;
        hv.x = silu_f(x[(base + n0 + 0) * HID + t]);
        hv.y = silu_f(x[(base + n0 + 1) * HID + t]);
        hv.z = silu_f(x[(base + n0 + 2) * HID + t]);
        hv.w = silu_f(x[(base + n0 + 3) * HID + t]);
        *reinterpret_cast<float4*>(&h0[t * 4]) = hv;
        __syncthreads();

        float4 acc = make_float4(sb1[t], sb1[t], sb1[t], sb1[t]);
        #pragma unroll 8
        for (int k = 0; k < 128; k++) {
            float w = __half2float(sW1h[k * 128 + t]);
            float4 h = *reinterpret_cast<const float4*>(&h0[k * 4]);
            acc.x = fmaf(h.x, w, acc.x);
            acc.y = fmaf(h.y, w, acc.y);
            acc.z = fmaf(h.z, w, acc.z);
            acc.w = fmaf(h.w, w, acc.w);
        }
        float4 s1 = make_float4(silu_f(acc.x), silu_f(acc.y), silu_f(acc.z), silu_f(acc.w));
        *reinterpret_cast<float4*>(&h1[t * 4]) = s1;
        __syncthreads();

        if (t < 32) {
            float4 a2 = make_float4(sb2[t], sb2[t], sb2[t], sb2[t]);
            #pragma unroll 8
            for (int k = 0; k < 128; k++) {
                float w = __half2float(sW2h[k * 32 + t]);
                float4 h = *reinterpret_cast<const float4*>(&h1[k * 4]);
                a2.x = fmaf(h.x, w, a2.x);
                a2.y = fmaf(h.y, w, a2.y);
                a2.z = fmaf(h.z, w, a2.z);
                a2.w = fmaf(h.w, w, a2.w);
            }
            g_xd[(base + n0 + 0) * DOWN + t] = a2.x;
            g_xd[(base + n0 + 1) * DOWN + t] = a2.y;
            g_xd[(base + n0 + 2) * DOWN + t] = a2.z;
            g_xd[(base + n0 + 3) * DOWN + t] = a2.w;
        }
        __syncthreads();
    }
}

// ---------------- mega role: coeffs MLP (256 thr, 64 rows) -----------------
// weights fp16 in smem; activations + accumulate fp32; 3 blocks/SM
__device__ __forceinline__ void co_part(int lb,
                                        const float* __restrict__ cin,
                                        const float* __restrict__ W1,
                                        const float* __restrict__ W2,
                                        char* smem) {
    __half* sW1h = reinterpret_cast<__half*>(smem);           // [k=64][col=128] 16384 B
    __half* sW2h = reinterpret_cast<__half*>(smem + 16384);   // [k=128][col=32]  8192 B
    float*  sX   = reinterpret_cast<float*>(smem + 24576);    // [k=64][row=64]  16384 B
    float*  sH   = reinterpret_cast<float*>(smem + 40960);    // [hid=128][pad68] 34816 B

    int tid = threadIdx.x;
    int rowbase = lb * 64;

    {
        const float4* W14 = reinterpret_cast<const float4*>(W1);
        uint2* v = reinterpret_cast<uint2*>(sW1h);
        #pragma unroll
        for (int i = tid; i < 2048; i += 256) {
            float4 w = W14[i];
            v[i] = pack_h4(w.x, w.y, w.z, w.w);
        }
        const float4* W24 = reinterpret_cast<const float4*>(W2);
        uint2* v2 = reinterpret_cast<uint2*>(sW2h);
        #pragma unroll
        for (int i = tid; i < 1024; i += 256) {
            float4 w = W24[i];
            v2[i] = pack_h4(w.x, w.y, w.z, w.w);
        }
    }

    {
        int r  = tid & 63;
        int kc = tid >> 6;
        const float4* cin4 = reinterpret_cast<const float4*>(cin + (size_t)(rowbase + r) * CO);
        #pragma unroll
        for (int m = 0; m < 4; m++) {
            float4 v = cin4[kc * 4 + m];
            int k0 = kc * 16 + m * 4;
            sX[(k0 + 0) * 64 + r] = silu_f(v.x);
            sX[(k0 + 1) * 64 + r] = silu_f(v.y);
            sX[(k0 + 2) * 64 + r] = silu_f(v.z);
            sX[(k0 + 3) * 64 + r] = silu_f(v.w);
        }
    }
    __syncthreads();

    int tr = tid & 15;
    int tc = tid >> 4;

    float acc[4][8];
    #pragma unroll
    for (int i = 0; i < 4; i++)
        #pragma unroll
        for (int j = 0; j < 8; j++) acc[i][j] = 0.f;

    const float4* sX4  = reinterpret_cast<const float4*>(sX);
    const uint4*  sW1q = reinterpret_cast<const uint4*>(sW1h);   // 16 uint4 per k-row
    #pragma unroll 4
    for (int k = 0; k < 64; k++) {
        float4 a  = sX4[k * 16 + tr];
        uint4  bq = sW1q[k * 16 + tc];           // 8 halfs: cols tc*8..+7
        float2 f0 = __half22float2(*reinterpret_cast<__half2*>(&bq.x));
        float2 f1 = __half22float2(*reinterpret_cast<__half2*>(&bq.y));
        float2 f2 = __half22float2(*reinterpret_cast<__half2*>(&bq.z));
        float2 f3 = __half22float2(*reinterpret_cast<__half2*>(&bq.w));
        float av[4] = {a.x, a.y, a.z, a.w};
        float bv[8] = {f0.x, f0.y, f1.x, f1.y, f2.x, f2.y, f3.x, f3.y};
        #pragma unroll
        for (int i = 0; i < 4; i++)
            #pragma unroll
            for (int j = 0; j < 8; j++)
                acc[i][j] = fmaf(av[i], bv[j], acc[i][j]);
    }

    float4* sH4 = reinterpret_cast<float4*>(sH);
    #pragma unroll
    for (int j = 0; j < 8; j++) {
        int col = tc * 8 + j;
        float4 v = make_float4(silu_f(acc[0][j]), silu_f(acc[1][j]),
                               silu_f(acc[2][j]), silu_f(acc[3][j]));
        sH4[col * 17 + tr] = v;
    }
    __syncthreads();

    float a20 = 0.f, a21 = 0.f, a22 = 0.f, a23 = 0.f;
    float a30 = 0.f, a31 = 0.f, a32 = 0.f, a33 = 0.f;
    const unsigned* sW2u = reinterpret_cast<const unsigned*>(sW2h);  // 16 per k-row
    #pragma unroll 8
    for (int k = 0; k < 128; k++) {
        float4 a = sH4[k * 17 + tr];
        unsigned bu = sW2u[k * 16 + tc];
        float2 b = __half22float2(*reinterpret_cast<__half2*>(&bu));
        a20 = fmaf(a.x, b.x, a20);
        a21 = fmaf(a.y, b.x, a21);
        a22 = fmaf(a.z, b.x, a22);
        a23 = fmaf(a.w, b.x, a23);
        a30 = fmaf(a.x, b.y, a30);
        a31 = fmaf(a.y, b.y, a31);
        a32 = fmaf(a.z, b.y, a32);
        a33 = fmaf(a.w, b.y, a33);
    }

    float* sOut = sX;   // sX dead after layer-1 sync
    int r0 = tr * 4;
    int c0 = tc * 2;
    sOut[(r0 + 0) * 32 + c0]     = a20;
    sOut[(r0 + 1) * 32 + c0]     = a21;
    sOut[(r0 + 2) * 32 + c0]     = a22;
    sOut[(r0 + 3) * 32 + c0]     = a23;
    sOut[(r0 + 0) * 32 + c0 + 1] = a30;
    sOut[(r0 + 1) * 32 + c0 + 1] = a31;
    sOut[(r0 + 2) * 32 + c0 + 1] = a32;
    sOut[(r0 + 3) * 32 + c0 + 1] = a33;
    __syncthreads();

    // epilogue: lane-contiguous layout: uint2 index w = l*4 + i
    const float4* sOut4 = reinterpret_cast<const float4*>(sOut);
    uint2* outh = reinterpret_cast<uint2*>(g_c);
    int nodebase = lb * 4;
    #pragma unroll
    for (int mm = 0; mm < 2; mm++) {
        int m  = tid + mm * 256;
        int q  = m >> 7;
        int w  = m & 127;
        int l  = w >> 2;          // chunk lane
        int i  = w & 3;           // quarter
        int rr = l >> 1;
        int hf = l & 1;
        float4 vv = sOut4[(q * 16 + rr) * 8 + hf * 4 + i];
        outh[(size_t)(nodebase + q) * 128 + w] = pack_h4(vv.x, vv.y, vv.z, vv.w);
    }
}

// ---------------- mega kernel: fill | node | co | aggzero ------------------
__global__ __launch_bounds__(256) void mega_kernel(
    const float* __restrict__ x,
    const float* __restrict__ coeffs,
    const int* __restrict__ e_ji,
    const int* __restrict__ idx_j,
    const int* __restrict__ idx_k,
    const int* __restrict__ e_kj,
    const float* __restrict__ Wn1,
    const float* __restrict__ bn1,
    const float* __restrict__ Wn2,
    const float* __restrict__ bn2,
    const float* __restrict__ Wc1,
    const float* __restrict__ Wc2) {
    extern __shared__ char smem[];
    int bid = blockIdx.x;
    if (bid < FILL_BLKS) {
        fill_part(bid, e_ji, idx_j, idx_k, e_kj);
    } else if (bid < FILL_BLKS + NODE_BLKS) {
        node_part(bid - FILL_BLKS, x, Wn1, bn1, Wn2, bn2, smem);
    } else if (bid < FILL_BLKS + NODE_BLKS + CO_BLKS) {
        co_part(bid - FILL_BLKS - NODE_BLKS, coeffs, Wc1, Wc2, smem);
    } else {
        agg_part(bid - FILL_BLKS - NODE_BLKS - CO_BLKS);
    }
}

// unpack one uint4 (8 halfs = 2 quarters) to 8 floats
__device__ __forceinline__ void unpack8(uint4 u, float* o) {
    float2 f0 = __half22float2(*reinterpret_cast<__half2*>(&u.x));
    float2 f1 = __half22float2(*reinterpret_cast<__half2*>(&u.y));
    float2 f2 = __half22float2(*reinterpret_cast<__half2*>(&u.z));
    float2 f3 = __half22float2(*reinterpret_cast<__half2*>(&u.w));
    o[0] = f0.x; o[1] = f0.y; o[2] = f1.x; o[3] = f1.y;
    o[4] = f2.x; o[5] = f2.y; o[6] = f3.x; o[7] = f3.y;
}

// ---------------- K3: fused triplet + edge + aggregation ------------------
// warp per edge; lane pair (2r, 2r+1) owns DR row r (16 h-values each).
// Packed slot record: one int4 load -> j, k, kj, t (2-stage L2 chain).
__global__ __launch_bounds__(256) void fused_edge_kernel(
    const float* __restrict__ robs,
    const float* __restrict__ shbs,
    const int* __restrict__ edge_index) {
    int e    = (blockIdx.x * blockDim.x + threadIdx.x) >> 5;
    int lane = threadIdx.x & 31;
    if (e >= N_EDGES) return;

    const uint4* cq = reinterpret_cast<const uint4*>(g_c);   // 64 uint4 per node
    int hr = lane >> 1;

    int n   = g_cnt[e];
    int src = edge_index[e];
    int dst = edge_index[N_EDGES + e];
    float wr = robs[e * DR + hr];
    const int4* sl = g_slot + e * SLOT_CAP;

    float tw[16];
    #pragma unroll
    for (int i = 0; i < 16; i++) tw[i] = 0.f;

    #pragma unroll 2
    for (int ii = 0; ii < n; ii++) {
        int4 rec = sl[ii];
        int j  = rec.x;
        int k  = rec.y;
        int kj = rec.z;
        int t  = rec.w;
        float w = shbs[t * DR + hr] * robs[kj * DR + hr];

        uint4 ka = cq[(size_t)k * 64 + lane * 2];
        uint4 kb = cq[(size_t)k * 64 + lane * 2 + 1];
        uint4 ja = cq[(size_t)j * 64 + lane * 2];
        uint4 jb = cq[(size_t)j * 64 + lane * 2 + 1];

        float a[16], b[16];
        unpack8(ka, a);     unpack8(kb, a + 8);
        unpack8(ja, b);     unpack8(jb, b + 8);

        float v[16];
        #pragma unroll
        for (int i = 0; i < 16; i++) v[i] = fmaf(a[i], b[i], a[i]);

        float p0 = 0.f, p1 = 0.f, p2 = 0.f, p3 = 0.f;
        #pragma unroll
        for (int i = 0; i < 4; i++) {
            p0 = fmaf(v[i*4+0], v[i*4+0], p0);
            p1 = fmaf(v[i*4+1], v[i*4+1], p1);
            p2 = fmaf(v[i*4+2], v[i*4+2], p2);
            p3 = fmaf(v[i*4+3], v[i*4+3], p3);
        }
        float ss = (p0 + p1) + (p2 + p3);
        ss += __shfl_xor_sync(0xffffffffu, ss, 1);
        float scale = w / fmaxf(sqrtf(ss), 1e-12f);
        #pragma unroll
        for (int i = 0; i < 16; i++) tw[i] = fmaf(scale, v[i], tw[i]);
    }

    // -------- edge interaction --------
    uint4 da = cq[(size_t)dst * 64 + lane * 2];
    uint4 db = cq[(size_t)dst * 64 + lane * 2 + 1];
    uint4 sa = cq[(size_t)src * 64 + lane * 2];
    uint4 sb = cq[(size_t)src * 64 + lane * 2 + 1];

    float a[16], b[16];
    unpack8(da, a);     unpack8(db, a + 8);
    unpack8(sa, b);     unpack8(sb, b + 8);

    float val[16];
    #pragma unroll
    for (int i = 0; i < 16; i++) val[i] = fmaf(a[i], b[i], a[i]) * tw[i];

    float p0 = 0.f, p1 = 0.f, p2 = 0.f, p3 = 0.f;
    #pragma unroll
    for (int i = 0; i < 4; i++) {
        p0 = fmaf(val[i*4+0], val[i*4+0], p0);
        p1 = fmaf(val[i*4+1], val[i*4+1], p1);
        p2 = fmaf(val[i*4+2], val[i*4+2], p2);
        p3 = fmaf(val[i*4+3], val[i*4+3], p3);
    }
    float ss = (p0 + p1) + (p2 + p3);
    ss += __shfl_xor_sync(0xffffffffu, ss, 1);
    float factor = wr / fmaxf(sqrtf(ss), 1e-12f);
    #pragma unroll
    for (int i = 0; i < 16; i++) val[i] *= factor;

    #pragma unroll
    for (int st = 0; st < 4; st++) {
        const int s  = 2 << st;
        const int n2 = 8 >> st;
        bool up = (lane & s) != 0;
        #pragma unroll
        for (int m = 0; m < n2; m++) {
            float send = up ? val[m] : val[m + n2];
            float recv = __shfl_xor_sync(0xffffffffu, send, s);
            val[m] = (up ? val[m + n2] : val[m]) + recv;
        }
    }
    float acc = val[0];
    int idx = ((lane >> 1) & 1) * 8 + ((lane >> 2) & 1) * 4 +
              ((lane >> 3) & 1) * 2 + ((lane >> 4) & 1);
    int h = (lane & 1) * 16 + idx;

    float sq = acc * acc;
    #pragma unroll
    for (int m = 1; m < 32; m <<= 1) sq += __shfl_xor_sync(0xffffffffu, sq, m);
    float rd = acc / fmaxf(sqrtf(sq), 1e-12f);

    atomicAdd(&g_agg[src * DOWN + h], g_xd[dst * DOWN + h] * rd);
}

// ---------------- K5: up-projection (4-way ILP) ----------------------------
__global__ void up_kernel(const float* __restrict__ Wup,
                          float* __restrict__ out) {
    __shared__ float sW[DOWN * HID];
    __shared__ float sA[16 * DOWN];
    int t = threadIdx.x;
    for (int i = t; i < DOWN * HID; i += 128) sW[i] = Wup[i];
    int base = blockIdx.x * 16;
    for (int i = t; i < 512; i += 128) sA[i] = g_agg[base * DOWN + i];
    __syncthreads();

    for (int n = 0; n < 16; n += 4) {
        float a0 = 0.f, a1 = 0.f, a2 = 0.f, a3 = 0.f;
        #pragma unroll 8
        for (int d = 0; d < DOWN; d++) {
            float w = sW[d * HID + t];
            a0 = fmaf(sA[(n + 0) * DOWN + d], w, a0);
            a1 = fmaf(sA[(n + 1) * DOWN + d], w, a1);
            a2 = fmaf(sA[(n + 2) * DOWN + d], w, a2);
            a3 = fmaf(sA[(n + 3) * DOWN + d], w, a3);
        }
        out[(base + n + 0) * HID + t] = a0;
        out[(base + n + 1) * HID + t] = a1;
        out[(base + n + 2) * HID + t] = a2;
        out[(base + n + 3) * HID + t] = a3;
    }
}

// ---------------- launch ---------------------------------------------------
extern "C" void kernel_launch(void* const* d_in, const int* in_sizes, int n_in,
                              void* d_out, int out_size) {
    const float* x      = (const float*)d_in[0];
    const float* robs   = (const float*)d_in[1];
    const float* shbs   = (const float*)d_in[2];
    const float* coeffs = (const float*)d_in[3];
    const int*   eidx   = (const int*)d_in[4];
    const int*   idx_j  = (const int*)d_in[5];
    const int*   idx_k  = (const int*)d_in[6];
    const int*   e_kj   = (const int*)d_in[7];
    const int*   e_ji   = (const int*)d_in[8];
    const float* Wn1    = (const float*)d_in[9];
    const float* bn1    = (const float*)d_in[10];
    const float* Wn2    = (const float*)d_in[11];
    const float* bn2    = (const float*)d_in[12];
    const float* Wc1    = (const float*)d_in[13];
    const float* Wc2    = (const float*)d_in[14];
    const float* Wup    = (const float*)d_in[15];
    float* out = (float*)d_out;

    cudaFuncSetAttribute(mega_kernel, cudaFuncAttributeMaxDynamicSharedMemorySize, MEGA_SMEM_BYTES);

    // zero g_cnt only (must precede fill atomics); g_agg zeroed inside mega
    init_kernel<<<(N_EDGES + 255) / 256, 256>>>();

    // fill + node MLP + coeffs MLP + agg-zero in one grid (independent outputs)
    mega_kernel<<<MEGA_BLKS, 256, MEGA_SMEM_BYTES>>>(x, coeffs, e_ji,
                                                     idx_j, idx_k, e_kj,
                                                     Wn1, bn1, Wn2, bn2, Wc1, Wc2);

    // fused triplet + edge + aggregation: warp per edge
    fused_edge_kernel<<<N_EDGES / 8, 256>>>(robs, shbs, eidx);

    // up-projection
    up_kernel<<<1250, 128>>>(Wup, out);
}